// round 5
// baseline (speedup 1.0000x reference)
#include <cuda_runtime.h>

// BilateralFilter: x [32, 3, 64, 512] f32 -> out [32, 4, 14, 64, 512] f32
// out[b, cls, k, z, a] = exp(-sqdist(b,k,z,a) * inv2theta2[cls])
// sqdist = sum_ch (x[b,ch,z,a] - nbr_k(x)[b,ch,z,a])^2, zero-padded 3x5
// neighborhood excluding center (K=14, dz-major/da-minor order).
// inv2theta2 = [2222.2222, 2222.2222, 5000, 5000] -> cls {0,1} == cls {2,3}
// up to 5000 = 2.25 * 2222.2222.
//
// R4 (resubmit after infra failure): force 4 blocks/SM (regs<=64) -- R3 showed
// occupancy directly buys DRAM throughput on this store-bound kernel
// (occ 21->32% gave 49->55% DRAM).

#define BZ 32
#define ZZ 64
#define AA 512
#define PLANE (ZZ * AA)          // 32768

__global__ __launch_bounds__(256, 4)
void bilateral_kernel(const float* __restrict__ x, float* __restrict__ out) {
    int tid = blockIdx.x * blockDim.x + threadIdx.x;
    // total threads = 32 * 64 * (512/4) = 262144
    int a4 = tid & 127;            // group of 4 along azimuth
    int z  = (tid >> 7) & 63;
    int b  = tid >> 13;
    int a0 = a4 << 2;

    const bool interior = (a4 != 0) & (a4 != 127);
    const float C1 = 2222.2222f;      // 1/(2*0.015^2); 5000 = 2.25 * C1

    // Per-channel row base for the CENTER row; neighbor rows offset by +/-512.
    const float* base0 = x + (b * 3) * PLANE + (z << 9) + a0;

    // Center quads per channel (4 pixels each).
    float c0[3], c1[3], c2[3], c3[3];
#pragma unroll
    for (int ch = 0; ch < 3; ch++) {
        const float4 v = *reinterpret_cast<const float4*>(base0 + ch * PLANE);
        c0[ch] = v.x; c1[ch] = v.y; c2[ch] = v.z; c3[ch] = v.w;
    }

    float* ob = out + (size_t)b * (4 * 14 * PLANE) + (z << 9) + a0;
    int k = 0;

#pragma unroll
    for (int dz = 0; dz < 3; dz++) {
        int zoff = (dz - 1) << 9;                 // -512, 0, +512
        bool zok = ((unsigned)(z - 1 + dz) < ZZ);

        // 8-wide window row (a0-2 .. a0+5) per channel, zero-padded.
        float win[3][8];
#pragma unroll
        for (int ch = 0; ch < 3; ch++) {
            const float* row = base0 + ch * PLANE + zoff;   // points at col a0
            if (zok & interior) {
                float4 v = *reinterpret_cast<const float4*>(row);
                win[ch][2] = v.x; win[ch][3] = v.y; win[ch][4] = v.z; win[ch][5] = v.w;
                win[ch][0] = row[-2];
                win[ch][1] = row[-1];
                win[ch][6] = row[4];
                win[ch][7] = row[5];
            } else if (zok) {
                float4 v = *reinterpret_cast<const float4*>(row);
                win[ch][2] = v.x; win[ch][3] = v.y; win[ch][4] = v.z; win[ch][5] = v.w;
                win[ch][0] = (a0 >= 2)     ? row[-2] : 0.f;
                win[ch][1] = (a0 >= 1)     ? row[-1] : 0.f;
                win[ch][6] = (a0 + 4 < AA) ? row[4]  : 0.f;
                win[ch][7] = (a0 + 5 < AA) ? row[5]  : 0.f;
            } else {
#pragma unroll
                for (int j = 0; j < 8; j++) win[ch][j] = 0.f;
            }
        }

#pragma unroll
        for (int da = 0; da < 5; da++) {
            if (dz == 1 && da == 2) continue;   // center excluded

            float sx = 0.f, sy = 0.f, sz = 0.f, sw = 0.f;
#pragma unroll
            for (int ch = 0; ch < 3; ch++) {
                float d0 = c0[ch] - win[ch][0 + da];
                float d1 = c1[ch] - win[ch][1 + da];
                float d2 = c2[ch] - win[ch][2 + da];
                float d3 = c3[ch] - win[ch][3 + da];
                sx += d0 * d0; sy += d1 * d1; sz += d2 * d2; sw += d3 * d3;
            }

            float t0 = -C1 * sx, t1 = -C1 * sy, t2 = -C1 * sz, t3 = -C1 * sw;
            float tmax = fmaxf(fmaxf(t0, t1), fmaxf(t2, t3));
            float4 e1 = make_float4(0.f, 0.f, 0.f, 0.f);
            float4 e2 = make_float4(0.f, 0.f, 0.f, 0.f);
            // expf underflows to 0 below ~-87.3; with N(0,1) inputs ~88% of
            // warp-iterations skip the MUFU work entirely.
            if (tmax > -88.0f) {
                e1.x = __expf(t0);          e1.y = __expf(t1);
                e1.z = __expf(t2);          e1.w = __expf(t3);
                e2.x = __expf(2.25f * t0);  e2.y = __expf(2.25f * t1);
                e2.z = __expf(2.25f * t2);  e2.w = __expf(2.25f * t3);
            }
            float* p = ob + k * PLANE;
            __stcs(reinterpret_cast<float4*>(p),              e1);  // class 0
            __stcs(reinterpret_cast<float4*>(p + 14 * PLANE), e1);  // class 1
            __stcs(reinterpret_cast<float4*>(p + 28 * PLANE), e2);  // class 2
            __stcs(reinterpret_cast<float4*>(p + 42 * PLANE), e2);  // class 3
            k++;
        }
    }
}

extern "C" void kernel_launch(void* const* d_in, const int* in_sizes, int n_in,
                              void* d_out, int out_size) {
    const float* x = (const float*)d_in[0];
    float* out = (float*)d_out;
    int total = BZ * ZZ * (AA / 4);          // 262144 threads
    int threads = 256;
    bilateral_kernel<<<total / threads, threads>>>(x, out);
}